// round 1
// baseline (speedup 1.0000x reference)
#include <cuda_runtime.h>
#include <math.h>

// Problem constants
#define NN   883
#define BB   64
#define TT   12
#define HIDN 64
#define EMBD 10
#define CIN0 65     // DIN(1) + HID(64)
#define CIN1 128    // HID + HID
#define HOR  12

// ---------------- scratch (device globals; no allocation allowed) -----------
__device__ float g_A[NN * NN];                       // adjacency
__device__ float g_Wg0[NN * 2 * CIN0 * 128];         // per-node gate W, layer0
__device__ float g_Wc0[NN * 2 * CIN0 * 64];          // per-node cand W, layer0
__device__ float g_Wg1[NN * 2 * CIN1 * 128];         // layer1
__device__ float g_Wc1[NN * 2 * CIN1 * 64];
__device__ float g_Bg0[NN * 128];
__device__ float g_Bc0[NN * 64];
__device__ float g_Bg1[NN * 128];
__device__ float g_Bc1[NN * 64];
__device__ float g_H[NN * BB * HIDN];                // hidden state [n][b][h]
__device__ float g_SEQ[TT * NN * BB * HIDN];         // layer0 outputs over time
__device__ float g_XIN[NN * BB * CIN1];              // gconv input  [n][b][c]
__device__ float g_AX[NN * BB * CIN1];               // A @ XIN
__device__ float g_ZR[NN * BB * 128];                // sigmoid(gate) z|r

// ---------------- adjacency: A = softmax(relu(E E^T), axis=1) ---------------
__global__ void __launch_bounds__(256) k_supports(const float* __restrict__ E,
                                                  float* __restrict__ A) {
    int n = blockIdx.x;
    int tid = threadIdx.x;
    __shared__ float row[NN];
    __shared__ float red[8];
    __shared__ float ssum;
    float en[EMBD];
#pragma unroll
    for (int d = 0; d < EMBD; d++) en[d] = E[n * EMBD + d];
    float lmax = -1e30f;
    for (int m = tid; m < NN; m += 256) {
        float s = 0.f;
#pragma unroll
        for (int d = 0; d < EMBD; d++) s = fmaf(en[d], E[m * EMBD + d], s);
        s = fmaxf(s, 0.f);
        row[m] = s;
        lmax = fmaxf(lmax, s);
    }
#pragma unroll
    for (int o = 16; o; o >>= 1) lmax = fmaxf(lmax, __shfl_xor_sync(0xffffffffu, lmax, o));
    if ((tid & 31) == 0) red[tid >> 5] = lmax;
    __syncthreads();
    if (tid == 0) {
        float mx = red[0];
        for (int w = 1; w < 8; w++) mx = fmaxf(mx, red[w]);
        red[0] = mx;
    }
    __syncthreads();
    float mx = red[0];
    __syncthreads();
    float lsum = 0.f;
    for (int m = tid; m < NN; m += 256) {
        float e = expf(row[m] - mx);
        row[m] = e;
        lsum += e;
    }
#pragma unroll
    for (int o = 16; o; o >>= 1) lsum += __shfl_xor_sync(0xffffffffu, lsum, o);
    if ((tid & 31) == 0) red[tid >> 5] = lsum;
    __syncthreads();
    if (tid == 0) {
        float s = 0.f;
        for (int w = 0; w < 8; w++) s += red[w];
        ssum = s;
    }
    __syncthreads();
    float inv = 1.f / ssum;
    for (int m = tid; m < NN; m += 256) A[n * NN + m] = row[m] * inv;
}

// ------------- per-node weight/bias pooling: out[n,rc] = E[n,:] @ pool[:,rc] -
__global__ void k_nodew(const float* __restrict__ E, const float* __restrict__ pool,
                        float* __restrict__ out, int RC) {
    long total = (long)NN * RC;
    long idx = (long)blockIdx.x * blockDim.x + threadIdx.x;
    if (idx >= total) return;
    int n = (int)(idx / RC);
    int rem = (int)(idx % RC);
    float s = 0.f;
#pragma unroll
    for (int d = 0; d < EMBD; d++) s = fmaf(E[n * EMBD + d], pool[(long)d * RC + rem], s);
    out[idx] = s;
}

__global__ void k_zero(float* __restrict__ p, long cnt) {
    long i = (long)blockIdx.x * blockDim.x + threadIdx.x;
    if (i < cnt) p[i] = 0.f;
}

// ---------------- build gconv input XIN[n][b][c] -----------------------------
// layer0: c==0 -> source[b,t,n,0]; else h (cand: z*h)
// layer1: c<64 -> SEQ[t][n][b][c];  else h (cand: z*h)
__global__ void k_build(const float* __restrict__ src, int t, int layer, int cand) {
    int Cin = layer == 0 ? CIN0 : CIN1;
    long total = (long)NN * BB * Cin;
    long idx = (long)blockIdx.x * blockDim.x + threadIdx.x;
    if (idx >= total) return;
    int c = (int)(idx % Cin);
    long nb = idx / Cin;
    int b = (int)(nb % BB);
    int n = (int)(nb / BB);
    int xw = (layer == 0) ? 1 : HIDN;
    float v;
    if (c < xw) {
        v = (layer == 0) ? src[((long)b * TT + t) * NN + n]
                         : g_SEQ[(((long)t * NN + n) * BB + b) * HIDN + c];
    } else {
        int j = c - xw;
        float h = g_H[((long)n * BB + b) * HIDN + j];
        if (cand) h *= g_ZR[((long)n * BB + b) * 128 + j];  // z = first half of zr
        v = h;
    }
    g_XIN[idx] = v;
}

// ---------------- dense SGEMM: C[M,Ncols] = A[M,K] @ X[K,Ncols] --------------
// 128x128 tile, BK=8, 256 threads, 8x8 register tile
__global__ void __launch_bounds__(256) k_sgemm(const float* __restrict__ A,
                                               const float* __restrict__ X,
                                               float* __restrict__ C,
                                               int M, int K, int Ncols) {
    __shared__ float As[8][128];
    __shared__ float Bs[8][128];
    int tid = threadIdx.x;
    int rowBase = blockIdx.y * 128;
    int colBase = blockIdx.x * 128;
    int trow = (tid >> 4) * 8;
    int tcol = (tid & 15) * 8;
    float acc[8][8];
#pragma unroll
    for (int i = 0; i < 8; i++)
#pragma unroll
        for (int j = 0; j < 8; j++) acc[i][j] = 0.f;

    for (int k0 = 0; k0 < K; k0 += 8) {
#pragma unroll
        for (int i = 0; i < 4; i++) {
            int idx = tid * 4 + i;
            int r = idx >> 3, c = idx & 7;
            int gr = rowBase + r, gc = k0 + c;
            As[c][r] = (gr < M && gc < K) ? A[(size_t)gr * K + gc] : 0.f;
        }
#pragma unroll
        for (int i = 0; i < 4; i++) {
            int idx = tid + i * 256;
            int r = idx >> 7, c = idx & 127;
            int gr = k0 + r, gc = colBase + c;
            Bs[r][c] = (gr < K && gc < Ncols) ? X[(size_t)gr * Ncols + gc] : 0.f;
        }
        __syncthreads();
#pragma unroll
        for (int k = 0; k < 8; k++) {
            float4 a0 = *(const float4*)&As[k][trow];
            float4 a1 = *(const float4*)&As[k][trow + 4];
            float4 b0 = *(const float4*)&Bs[k][tcol];
            float4 b1 = *(const float4*)&Bs[k][tcol + 4];
            float a[8] = {a0.x, a0.y, a0.z, a0.w, a1.x, a1.y, a1.z, a1.w};
            float b[8] = {b0.x, b0.y, b0.z, b0.w, b1.x, b1.y, b1.z, b1.w};
#pragma unroll
            for (int i = 0; i < 8; i++)
#pragma unroll
                for (int j = 0; j < 8; j++) acc[i][j] = fmaf(a[i], b[j], acc[i][j]);
        }
        __syncthreads();
    }
#pragma unroll
    for (int i = 0; i < 8; i++) {
        int gr = rowBase + trow + i;
        if (gr < M) {
#pragma unroll
            for (int j = 0; j < 8; j++) {
                int gc = colBase + tcol + j;
                if (gc < Ncols) C[(size_t)gr * Ncols + gc] = acc[i][j];
            }
        }
    }
}

// -------- per-node batched GEMM with fused gate/candidate epilogue -----------
// One block per node n. O[64, COUT] = [XIN | AX][64, 2*Cin] @ W[n][2*Cin, COUT]
template <int COUT, bool CAND>
__global__ void __launch_bounds__(256) k_pngemm(const float* __restrict__ XIN,
                                                const float* __restrict__ AX,
                                                const float* __restrict__ W,
                                                const float* __restrict__ Bias,
                                                float* __restrict__ ZR,
                                                float* __restrict__ H,
                                                float* __restrict__ SEQOUT,
                                                int Cin) {
    const int n = blockIdx.x;
    const int Kd = 2 * Cin;
    const int tid = threadIdx.x;
    __shared__ float Xs[16][64];
    __shared__ float Ws[16][COUT];
    constexpr int CW = COUT / 16;           // 8 (gate) or 4 (cand)
    const int rg = tid >> 4;                // row group: rows rg*4..rg*4+3
    const int cg = tid & 15;                // col group: cols cg*CW..
    float acc[4][CW];
#pragma unroll
    for (int i = 0; i < 4; i++)
#pragma unroll
        for (int j = 0; j < CW; j++) acc[i][j] = 0.f;

    const float* Wn = W + (size_t)n * Kd * COUT;
    const float* Xn = XIN + (size_t)n * BB * Cin;
    const float* An = AX + (size_t)n * BB * Cin;

    for (int k0 = 0; k0 < Kd; k0 += 16) {
#pragma unroll
        for (int i = 0; i < 4; i++) {
            int idx = tid * 4 + i;           // 0..1023 over 64x16
            int b = idx >> 4, c = idx & 15;
            int kk = k0 + c;
            float v = 0.f;
            if (kk < Kd) v = (kk < Cin) ? Xn[b * Cin + kk] : An[b * Cin + kk - Cin];
            Xs[c][b] = v;
        }
        constexpr int WL = 16 * COUT / 256;  // 8 or 4
#pragma unroll
        for (int i = 0; i < WL; i++) {
            int idx = tid + i * 256;
            int r = idx / COUT, c = idx % COUT;
            int kk = k0 + r;
            Ws[r][c] = (kk < Kd) ? Wn[(size_t)kk * COUT + c] : 0.f;
        }
        __syncthreads();
#pragma unroll
        for (int k = 0; k < 16; k++) {
            float4 av = *(const float4*)&Xs[k][rg * 4];
            float a[4] = {av.x, av.y, av.z, av.w};
            float bb[CW];
#pragma unroll
            for (int j = 0; j < CW; j++) bb[j] = Ws[k][cg * CW + j];
#pragma unroll
            for (int i = 0; i < 4; i++)
#pragma unroll
                for (int j = 0; j < CW; j++) acc[i][j] = fmaf(a[i], bb[j], acc[i][j]);
        }
        __syncthreads();
    }

#pragma unroll
    for (int i = 0; i < 4; i++) {
        int b = rg * 4 + i;
#pragma unroll
        for (int j = 0; j < CW; j++) {
            int o = cg * CW + j;
            float v = acc[i][j] + Bias[n * COUT + o];
            if (!CAND) {
                ZR[((size_t)n * BB + b) * 128 + o] = 1.f / (1.f + expf(-v));
            } else {
                float hc = tanhf(v);
                float r = ZR[((size_t)n * BB + b) * 128 + 64 + o];
                size_t hix = ((size_t)n * BB + b) * HIDN + o;
                float hn = r * H[hix] + (1.f - r) * hc;
                H[hix] = hn;
                if (SEQOUT) SEQOUT[hix] = hn;
            }
        }
    }
}

// ---------------- final projection -------------------------------------------
// out[b, o, n, 0] = H[n,b,:] . conv_w[o,:] + conv_b[o]
__global__ void k_final(const float* __restrict__ H, const float* __restrict__ cw,
                        const float* __restrict__ cb, float* __restrict__ out) {
    int idx = blockIdx.x * blockDim.x + threadIdx.x;
    if (idx >= BB * NN) return;
    int n = idx % NN, b = idx / NN;
    const float* h = H + ((size_t)n * BB + b) * HIDN;
    float hv[HIDN];
#pragma unroll
    for (int j = 0; j < HIDN; j++) hv[j] = h[j];
#pragma unroll
    for (int o = 0; o < HOR; o++) {
        float s = cb[o];
#pragma unroll
        for (int j = 0; j < HIDN; j++) s = fmaf(hv[j], cw[o * HIDN + j], s);
        out[((size_t)b * HOR + o) * NN + n] = s;
    }
}

// =============================================================================
extern "C" void kernel_launch(void* const* d_in, const int* in_sizes, int n_in,
                              void* d_out, int out_size) {
    const float* src = (const float*)d_in[0];   // [B,T,N,1]
    const float* E   = (const float*)d_in[1];   // [N,EMB]
    const float* w0g = (const float*)d_in[2];
    const float* b0g = (const float*)d_in[3];
    const float* w0c = (const float*)d_in[4];
    const float* b0c = (const float*)d_in[5];
    const float* w1g = (const float*)d_in[6];
    const float* b1g = (const float*)d_in[7];
    const float* w1c = (const float*)d_in[8];
    const float* b1c = (const float*)d_in[9];
    const float* cw  = (const float*)d_in[10];
    const float* cb  = (const float*)d_in[11];
    float* out = (float*)d_out;

    float *A, *Wg0, *Wc0, *Wg1, *Wc1, *Bg0, *Bc0, *Bg1, *Bc1;
    float *H, *SEQ, *XIN, *AX, *ZR;
    cudaGetSymbolAddress((void**)&A, g_A);
    cudaGetSymbolAddress((void**)&Wg0, g_Wg0);
    cudaGetSymbolAddress((void**)&Wc0, g_Wc0);
    cudaGetSymbolAddress((void**)&Wg1, g_Wg1);
    cudaGetSymbolAddress((void**)&Wc1, g_Wc1);
    cudaGetSymbolAddress((void**)&Bg0, g_Bg0);
    cudaGetSymbolAddress((void**)&Bc0, g_Bc0);
    cudaGetSymbolAddress((void**)&Bg1, g_Bg1);
    cudaGetSymbolAddress((void**)&Bc1, g_Bc1);
    cudaGetSymbolAddress((void**)&H, g_H);
    cudaGetSymbolAddress((void**)&SEQ, g_SEQ);
    cudaGetSymbolAddress((void**)&XIN, g_XIN);
    cudaGetSymbolAddress((void**)&AX, g_AX);
    cudaGetSymbolAddress((void**)&ZR, g_ZR);

    // 1) adjacency
    k_supports<<<NN, 256>>>(E, A);

    // 2) per-node weights + biases
    auto launch_nodew = [&](const float* pool, float* dst, int RC) {
        long total = (long)NN * RC;
        k_nodew<<<(int)((total + 255) / 256), 256>>>(E, pool, dst, RC);
    };
    launch_nodew(w0g, Wg0, 2 * CIN0 * 128);
    launch_nodew(w0c, Wc0, 2 * CIN0 * 64);
    launch_nodew(w1g, Wg1, 2 * CIN1 * 128);
    launch_nodew(w1c, Wc1, 2 * CIN1 * 64);
    launch_nodew(b0g, Bg0, 128);
    launch_nodew(b0c, Bc0, 64);
    launch_nodew(b1g, Bg1, 128);
    launch_nodew(b1c, Bc1, 64);

    // 3) two stacked GRU-gconv layers over T steps
    for (int layer = 0; layer < 2; layer++) {
        int Cin = layer ? CIN1 : CIN0;
        int ncols = BB * Cin;
        long hcnt = (long)NN * BB * HIDN;
        k_zero<<<(int)((hcnt + 255) / 256), 256>>>(H, hcnt);

        const float* Wg = layer ? Wg1 : Wg0;
        const float* Wc = layer ? Wc1 : Wc0;
        const float* Bg = layer ? Bg1 : Bg0;
        const float* Bc = layer ? Bc1 : Bc0;

        long btotal = (long)NN * BB * Cin;
        int bblocks = (int)((btotal + 255) / 256);
        dim3 gg((ncols + 127) / 128, (NN + 127) / 128);

        for (int t = 0; t < TT; t++) {
            // gate gconv
            k_build<<<bblocks, 256>>>(src, t, layer, 0);
            k_sgemm<<<gg, 256>>>(A, XIN, AX, NN, NN, ncols);
            k_pngemm<128, false><<<NN, 256>>>(XIN, AX, Wg, Bg, ZR, H, nullptr, Cin);
            // candidate gconv + GRU update
            k_build<<<bblocks, 256>>>(src, t, layer, 1);
            k_sgemm<<<gg, 256>>>(A, XIN, AX, NN, NN, ncols);
            float* seqout = (layer == 0) ? (SEQ + (size_t)t * NN * BB * HIDN) : nullptr;
            k_pngemm<64, true><<<NN, 256>>>(XIN, AX, Wc, Bc, ZR, H, seqout, Cin);
        }
    }

    // 4) output head
    k_final<<<(BB * NN + 255) / 256, 256>>>(H, cw, cb, out);
}

// round 2
// speedup vs baseline: 1.0013x; 1.0013x over previous
#include <cuda_runtime.h>
#include <math.h>

// Problem constants
#define NN   883
#define BB   64
#define TT   12
#define HIDN 64
#define EMBD 10
#define CIN0 65     // DIN(1) + HID(64)
#define CIN1 128    // HID + HID
#define HOR  12

// ---------------- scratch (device globals; no allocation allowed) -----------
__device__ float g_A[NN * NN];                       // adjacency
__device__ float g_Wg0[NN * 2 * CIN0 * 128];         // per-node gate W, layer0
__device__ float g_Wc0[NN * 2 * CIN0 * 64];          // per-node cand W, layer0
__device__ float g_Wg1[NN * 2 * CIN1 * 128];         // layer1
__device__ float g_Wc1[NN * 2 * CIN1 * 64];
__device__ float g_Bg0[NN * 128];
__device__ float g_Bc0[NN * 64];
__device__ float g_Bg1[NN * 128];
__device__ float g_Bc1[NN * 64];
__device__ float g_H[NN * BB * HIDN];                // hidden state [n][b][h]
__device__ float g_SEQ[TT * NN * BB * HIDN];         // layer0 outputs over time
__device__ float g_XIN[NN * BB * CIN1];              // gconv input  [n][b][c]
__device__ float g_AX[NN * BB * CIN1];               // A @ XIN
__device__ float g_ZR[NN * BB * 128];                // sigmoid(gate) z|r

// ---------------- adjacency: A = softmax(relu(E E^T), axis=1) ---------------
__global__ void __launch_bounds__(256) k_supports(const float* __restrict__ E,
                                                  float* __restrict__ A) {
    int n = blockIdx.x;
    int tid = threadIdx.x;
    __shared__ float row[NN];
    __shared__ float red[8];
    __shared__ float ssum;
    float en[EMBD];
#pragma unroll
    for (int d = 0; d < EMBD; d++) en[d] = E[n * EMBD + d];
    float lmax = -1e30f;
    for (int m = tid; m < NN; m += 256) {
        float s = 0.f;
#pragma unroll
        for (int d = 0; d < EMBD; d++) s = fmaf(en[d], E[m * EMBD + d], s);
        s = fmaxf(s, 0.f);
        row[m] = s;
        lmax = fmaxf(lmax, s);
    }
#pragma unroll
    for (int o = 16; o; o >>= 1) lmax = fmaxf(lmax, __shfl_xor_sync(0xffffffffu, lmax, o));
    if ((tid & 31) == 0) red[tid >> 5] = lmax;
    __syncthreads();
    if (tid == 0) {
        float mx = red[0];
        for (int w = 1; w < 8; w++) mx = fmaxf(mx, red[w]);
        red[0] = mx;
    }
    __syncthreads();
    float mx = red[0];
    __syncthreads();
    float lsum = 0.f;
    for (int m = tid; m < NN; m += 256) {
        float e = expf(row[m] - mx);
        row[m] = e;
        lsum += e;
    }
#pragma unroll
    for (int o = 16; o; o >>= 1) lsum += __shfl_xor_sync(0xffffffffu, lsum, o);
    if ((tid & 31) == 0) red[tid >> 5] = lsum;
    __syncthreads();
    if (tid == 0) {
        float s = 0.f;
        for (int w = 0; w < 8; w++) s += red[w];
        ssum = s;
    }
    __syncthreads();
    float inv = 1.f / ssum;
    for (int m = tid; m < NN; m += 256) A[n * NN + m] = row[m] * inv;
}

// ------------- per-node weight/bias pooling: out[n,rc] = E[n,:] @ pool[:,rc] -
__global__ void k_nodew(const float* __restrict__ E, const float* __restrict__ pool,
                        float* __restrict__ out, int RC) {
    long total = (long)NN * RC;
    long idx = (long)blockIdx.x * blockDim.x + threadIdx.x;
    if (idx >= total) return;
    int n = (int)(idx / RC);
    int rem = (int)(idx % RC);
    float s = 0.f;
#pragma unroll
    for (int d = 0; d < EMBD; d++) s = fmaf(E[n * EMBD + d], pool[(long)d * RC + rem], s);
    out[idx] = s;
}

__global__ void k_zero(float* __restrict__ p, long cnt) {
    long i = (long)blockIdx.x * blockDim.x + threadIdx.x;
    if (i < cnt) p[i] = 0.f;
}

// ---------------- build gconv input XIN[n][b][c] -----------------------------
// layer0: c==0 -> source[b,t,n,0]; else h (cand: z*h)
// layer1: c<64 -> SEQ[t][n][b][c];  else h (cand: z*h)
__global__ void k_build(const float* __restrict__ src, int t, int layer, int cand) {
    int Cin = layer == 0 ? CIN0 : CIN1;
    long total = (long)NN * BB * Cin;
    long idx = (long)blockIdx.x * blockDim.x + threadIdx.x;
    if (idx >= total) return;
    int c = (int)(idx % Cin);
    long nb = idx / Cin;
    int b = (int)(nb % BB);
    int n = (int)(nb / BB);
    int xw = (layer == 0) ? 1 : HIDN;
    float v;
    if (c < xw) {
        v = (layer == 0) ? src[((long)b * TT + t) * NN + n]
                         : g_SEQ[(((long)t * NN + n) * BB + b) * HIDN + c];
    } else {
        int j = c - xw;
        float h = g_H[((long)n * BB + b) * HIDN + j];
        if (cand) h *= g_ZR[((long)n * BB + b) * 128 + j];  // z = first half of zr
        v = h;
    }
    g_XIN[idx] = v;
}

// ---------------- dense SGEMM: C[M,Ncols] = A[M,K] @ X[K,Ncols] --------------
// 128x128 tile, BK=8, 256 threads, 8x8 register tile
__global__ void __launch_bounds__(256) k_sgemm(const float* __restrict__ A,
                                               const float* __restrict__ X,
                                               float* __restrict__ C,
                                               int M, int K, int Ncols) {
    __shared__ float As[8][128];
    __shared__ float Bs[8][128];
    int tid = threadIdx.x;
    int rowBase = blockIdx.y * 128;
    int colBase = blockIdx.x * 128;
    int trow = (tid >> 4) * 8;
    int tcol = (tid & 15) * 8;
    float acc[8][8];
#pragma unroll
    for (int i = 0; i < 8; i++)
#pragma unroll
        for (int j = 0; j < 8; j++) acc[i][j] = 0.f;

    for (int k0 = 0; k0 < K; k0 += 8) {
#pragma unroll
        for (int i = 0; i < 4; i++) {
            int idx = tid * 4 + i;
            int r = idx >> 3, c = idx & 7;
            int gr = rowBase + r, gc = k0 + c;
            As[c][r] = (gr < M && gc < K) ? A[(size_t)gr * K + gc] : 0.f;
        }
#pragma unroll
        for (int i = 0; i < 4; i++) {
            int idx = tid + i * 256;
            int r = idx >> 7, c = idx & 127;
            int gr = k0 + r, gc = colBase + c;
            Bs[r][c] = (gr < K && gc < Ncols) ? X[(size_t)gr * Ncols + gc] : 0.f;
        }
        __syncthreads();
#pragma unroll
        for (int k = 0; k < 8; k++) {
            float4 a0 = *(const float4*)&As[k][trow];
            float4 a1 = *(const float4*)&As[k][trow + 4];
            float4 b0 = *(const float4*)&Bs[k][tcol];
            float4 b1 = *(const float4*)&Bs[k][tcol + 4];
            float a[8] = {a0.x, a0.y, a0.z, a0.w, a1.x, a1.y, a1.z, a1.w};
            float b[8] = {b0.x, b0.y, b0.z, b0.w, b1.x, b1.y, b1.z, b1.w};
#pragma unroll
            for (int i = 0; i < 8; i++)
#pragma unroll
                for (int j = 0; j < 8; j++) acc[i][j] = fmaf(a[i], b[j], acc[i][j]);
        }
        __syncthreads();
    }
#pragma unroll
    for (int i = 0; i < 8; i++) {
        int gr = rowBase + trow + i;
        if (gr < M) {
#pragma unroll
            for (int j = 0; j < 8; j++) {
                int gc = colBase + tcol + j;
                if (gc < Ncols) C[(size_t)gr * Ncols + gc] = acc[i][j];
            }
        }
    }
}

// -------- per-node batched GEMM with fused gate/candidate epilogue -----------
// One block per node n. O[64, COUT] = [XIN | AX][64, 2*Cin] @ W[n][2*Cin, COUT]
template <int COUT, bool CAND>
__global__ void __launch_bounds__(256) k_pngemm(const float* __restrict__ XIN,
                                                const float* __restrict__ AX,
                                                const float* __restrict__ W,
                                                const float* __restrict__ Bias,
                                                float* __restrict__ ZR,
                                                float* __restrict__ H,
                                                float* __restrict__ SEQOUT,
                                                int Cin) {
    const int n = blockIdx.x;
    const int Kd = 2 * Cin;
    const int tid = threadIdx.x;
    __shared__ float Xs[16][64];
    __shared__ float Ws[16][COUT];
    constexpr int CW = COUT / 16;           // 8 (gate) or 4 (cand)
    const int rg = tid >> 4;                // row group: rows rg*4..rg*4+3
    const int cg = tid & 15;                // col group: cols cg*CW..
    float acc[4][CW];
#pragma unroll
    for (int i = 0; i < 4; i++)
#pragma unroll
        for (int j = 0; j < CW; j++) acc[i][j] = 0.f;

    const float* Wn = W + (size_t)n * Kd * COUT;
    const float* Xn = XIN + (size_t)n * BB * Cin;
    const float* An = AX + (size_t)n * BB * Cin;

    for (int k0 = 0; k0 < Kd; k0 += 16) {
#pragma unroll
        for (int i = 0; i < 4; i++) {
            int idx = tid * 4 + i;           // 0..1023 over 64x16
            int b = idx >> 4, c = idx & 15;
            int kk = k0 + c;
            float v = 0.f;
            if (kk < Kd) v = (kk < Cin) ? Xn[b * Cin + kk] : An[b * Cin + kk - Cin];
            Xs[c][b] = v;
        }
        constexpr int WL = 16 * COUT / 256;  // 8 or 4
#pragma unroll
        for (int i = 0; i < WL; i++) {
            int idx = tid + i * 256;
            int r = idx / COUT, c = idx % COUT;
            int kk = k0 + r;
            Ws[r][c] = (kk < Kd) ? Wn[(size_t)kk * COUT + c] : 0.f;
        }
        __syncthreads();
#pragma unroll
        for (int k = 0; k < 16; k++) {
            float4 av = *(const float4*)&Xs[k][rg * 4];
            float a[4] = {av.x, av.y, av.z, av.w};
            float bb[CW];
#pragma unroll
            for (int j = 0; j < CW; j++) bb[j] = Ws[k][cg * CW + j];
#pragma unroll
            for (int i = 0; i < 4; i++)
#pragma unroll
                for (int j = 0; j < CW; j++) acc[i][j] = fmaf(a[i], bb[j], acc[i][j]);
        }
        __syncthreads();
    }

#pragma unroll
    for (int i = 0; i < 4; i++) {
        int b = rg * 4 + i;
#pragma unroll
        for (int j = 0; j < CW; j++) {
            int o = cg * CW + j;
            float v = acc[i][j] + Bias[n * COUT + o];
            if (!CAND) {
                ZR[((size_t)n * BB + b) * 128 + o] = 1.f / (1.f + expf(-v));
            } else {
                float hc = tanhf(v);
                float r = ZR[((size_t)n * BB + b) * 128 + 64 + o];
                size_t hix = ((size_t)n * BB + b) * HIDN + o;
                float hn = r * H[hix] + (1.f - r) * hc;
                H[hix] = hn;
                if (SEQOUT) SEQOUT[hix] = hn;
            }
        }
    }
}

// ---------------- final projection -------------------------------------------
// out[b, o, n, 0] = H[n,b,:] . conv_w[o,:] + conv_b[o]
__global__ void k_final(const float* __restrict__ H, const float* __restrict__ cw,
                        const float* __restrict__ cb, float* __restrict__ out) {
    int idx = blockIdx.x * blockDim.x + threadIdx.x;
    if (idx >= BB * NN) return;
    int n = idx % NN, b = idx / NN;
    const float* h = H + ((size_t)n * BB + b) * HIDN;
    float hv[HIDN];
#pragma unroll
    for (int j = 0; j < HIDN; j++) hv[j] = h[j];
#pragma unroll
    for (int o = 0; o < HOR; o++) {
        float s = cb[o];
#pragma unroll
        for (int j = 0; j < HIDN; j++) s = fmaf(hv[j], cw[o * HIDN + j], s);
        out[((size_t)b * HOR + o) * NN + n] = s;
    }
}

// =============================================================================
extern "C" void kernel_launch(void* const* d_in, const int* in_sizes, int n_in,
                              void* d_out, int out_size) {
    const float* src = (const float*)d_in[0];   // [B,T,N,1]
    const float* E   = (const float*)d_in[1];   // [N,EMB]
    const float* w0g = (const float*)d_in[2];
    const float* b0g = (const float*)d_in[3];
    const float* w0c = (const float*)d_in[4];
    const float* b0c = (const float*)d_in[5];
    const float* w1g = (const float*)d_in[6];
    const float* b1g = (const float*)d_in[7];
    const float* w1c = (const float*)d_in[8];
    const float* b1c = (const float*)d_in[9];
    const float* cw  = (const float*)d_in[10];
    const float* cb  = (const float*)d_in[11];
    float* out = (float*)d_out;

    float *A, *Wg0, *Wc0, *Wg1, *Wc1, *Bg0, *Bc0, *Bg1, *Bc1;
    float *H, *SEQ, *XIN, *AX, *ZR;
    cudaGetSymbolAddress((void**)&A, g_A);
    cudaGetSymbolAddress((void**)&Wg0, g_Wg0);
    cudaGetSymbolAddress((void**)&Wc0, g_Wc0);
    cudaGetSymbolAddress((void**)&Wg1, g_Wg1);
    cudaGetSymbolAddress((void**)&Wc1, g_Wc1);
    cudaGetSymbolAddress((void**)&Bg0, g_Bg0);
    cudaGetSymbolAddress((void**)&Bc0, g_Bc0);
    cudaGetSymbolAddress((void**)&Bg1, g_Bg1);
    cudaGetSymbolAddress((void**)&Bc1, g_Bc1);
    cudaGetSymbolAddress((void**)&H, g_H);
    cudaGetSymbolAddress((void**)&SEQ, g_SEQ);
    cudaGetSymbolAddress((void**)&XIN, g_XIN);
    cudaGetSymbolAddress((void**)&AX, g_AX);
    cudaGetSymbolAddress((void**)&ZR, g_ZR);

    // 1) adjacency
    k_supports<<<NN, 256>>>(E, A);

    // 2) per-node weights + biases
    auto launch_nodew = [&](const float* pool, float* dst, int RC) {
        long total = (long)NN * RC;
        k_nodew<<<(int)((total + 255) / 256), 256>>>(E, pool, dst, RC);
    };
    launch_nodew(w0g, Wg0, 2 * CIN0 * 128);
    launch_nodew(w0c, Wc0, 2 * CIN0 * 64);
    launch_nodew(w1g, Wg1, 2 * CIN1 * 128);
    launch_nodew(w1c, Wc1, 2 * CIN1 * 64);
    launch_nodew(b0g, Bg0, 128);
    launch_nodew(b0c, Bc0, 64);
    launch_nodew(b1g, Bg1, 128);
    launch_nodew(b1c, Bc1, 64);

    // 3) two stacked GRU-gconv layers over T steps
    for (int layer = 0; layer < 2; layer++) {
        int Cin = layer ? CIN1 : CIN0;
        int ncols = BB * Cin;
        long hcnt = (long)NN * BB * HIDN;
        k_zero<<<(int)((hcnt + 255) / 256), 256>>>(H, hcnt);

        const float* Wg = layer ? Wg1 : Wg0;
        const float* Wc = layer ? Wc1 : Wc0;
        const float* Bg = layer ? Bg1 : Bg0;
        const float* Bc = layer ? Bc1 : Bc0;

        long btotal = (long)NN * BB * Cin;
        int bblocks = (int)((btotal + 255) / 256);
        dim3 gg((ncols + 127) / 128, (NN + 127) / 128);

        for (int t = 0; t < TT; t++) {
            // gate gconv
            k_build<<<bblocks, 256>>>(src, t, layer, 0);
            k_sgemm<<<gg, 256>>>(A, XIN, AX, NN, NN, ncols);
            k_pngemm<128, false><<<NN, 256>>>(XIN, AX, Wg, Bg, ZR, H, nullptr, Cin);
            // candidate gconv + GRU update
            k_build<<<bblocks, 256>>>(src, t, layer, 1);
            k_sgemm<<<gg, 256>>>(A, XIN, AX, NN, NN, ncols);
            float* seqout = (layer == 0) ? (SEQ + (size_t)t * NN * BB * HIDN) : nullptr;
            k_pngemm<64, true><<<NN, 256>>>(XIN, AX, Wc, Bc, ZR, H, seqout, Cin);
        }
    }

    // 4) output head
    k_final<<<(BB * NN + 255) / 256, 256>>>(H, cw, cb, out);
}

// round 3
// speedup vs baseline: 2.1499x; 2.1472x over previous
#include <cuda_runtime.h>
#include <cuda_bf16.h>
#include <math.h>

#define NN 883
#define NP 896
#define BB 64
#define TT 12
#define HID 64
#define EMBD 10
#define NB 4096
#define NCSEQ 49152
#define NC0 768
typedef __nv_bfloat16 bf16;

__device__ bf16  g_Ahi[NP * NP];
__device__ bf16  g_Alo[NP * NP];
__device__ float g_Wg0[NN * 130 * 128];
__device__ float g_Wc0[NN * 130 * 64];
__device__ float g_Wg1[NN * 256 * 128];
__device__ float g_Wc1[NN * 256 * 64];
__device__ float g_Bg0[NN * 128];
__device__ float g_Bc0[NN * 64];
__device__ float g_Bg1[NN * 128];
__device__ float g_Bc1[NN * 64];
__device__ float g_H[NN * NB];
__device__ bf16  g_Hhi[NP * NB];
__device__ bf16  g_Hlo[NP * NB];
__device__ float g_ZH[NN * NB];
__device__ bf16  g_ZHhi[NP * NB];
__device__ bf16  g_ZHlo[NP * NB];
__device__ float g_R[NN * NB];
__device__ float g_AH[NP * NB];
__device__ float g_AZH[NP * NB];
__device__ float g_SEQ[(size_t)NN * NCSEQ];
__device__ bf16  g_SEQhi[(size_t)NP * NCSEQ];
__device__ bf16  g_SEQlo[(size_t)NP * NCSEQ];
__device__ float g_ASEQ[(size_t)NP * NCSEQ];
__device__ bf16  g_X0hi[NP * NC0];
__device__ bf16  g_X0lo[NP * NC0];
__device__ float g_AX0[NP * NC0];

__device__ __forceinline__ void bsplit(float v, bf16& hi, bf16& lo) {
    hi = __float2bfloat16_rn(v);
    lo = __float2bfloat16_rn(v - __bfloat162float(hi));
}
__device__ __forceinline__ void cp16(void* s, const void* g) {
    unsigned sa = (unsigned)__cvta_generic_to_shared(s);
    asm volatile("cp.async.cg.shared.global [%0], [%1], 16;" :: "r"(sa), "l"(g));
}
__device__ __forceinline__ void ldsm4(unsigned* r, unsigned a) {
    asm volatile("ldmatrix.sync.aligned.m8n8.x4.shared.b16 {%0,%1,%2,%3}, [%4];"
                 : "=r"(r[0]), "=r"(r[1]), "=r"(r[2]), "=r"(r[3]) : "r"(a));
}
__device__ __forceinline__ void ldsm4t(unsigned* r, unsigned a) {
    asm volatile("ldmatrix.sync.aligned.m8n8.x4.trans.shared.b16 {%0,%1,%2,%3}, [%4];"
                 : "=r"(r[0]), "=r"(r[1]), "=r"(r[2]), "=r"(r[3]) : "r"(a));
}
__device__ __forceinline__ void mma16816(float* c, const unsigned* a, const unsigned* b) {
    asm volatile(
        "mma.sync.aligned.m16n8k16.row.col.f32.bf16.bf16.f32 "
        "{%0,%1,%2,%3},{%4,%5,%6,%7},{%8,%9},{%0,%1,%2,%3};"
        : "+f"(c[0]), "+f"(c[1]), "+f"(c[2]), "+f"(c[3])
        : "r"(a[0]), "r"(a[1]), "r"(a[2]), "r"(a[3]), "r"(b[0]), "r"(b[1]));
}

// adjacency rows -> bf16 hi/lo, padded to 896x896
__global__ void __launch_bounds__(256) k_supports(const float* __restrict__ E,
                                                  bf16* __restrict__ Ahi,
                                                  bf16* __restrict__ Alo) {
    int n = blockIdx.x, tid = threadIdx.x;
    if (n >= NN) {
        for (int m = tid; m < NP; m += 256) { Ahi[n * NP + m] = __float2bfloat16(0.f); Alo[n * NP + m] = __float2bfloat16(0.f); }
        return;
    }
    __shared__ float row[NN];
    __shared__ float red[8];
    __shared__ float ssum;
    float en[EMBD];
#pragma unroll
    for (int d = 0; d < EMBD; d++) en[d] = E[n * EMBD + d];
    float lmax = -1e30f;
    for (int m = tid; m < NN; m += 256) {
        float s = 0.f;
#pragma unroll
        for (int d = 0; d < EMBD; d++) s = fmaf(en[d], E[m * EMBD + d], s);
        s = fmaxf(s, 0.f);
        row[m] = s;
        lmax = fmaxf(lmax, s);
    }
#pragma unroll
    for (int o = 16; o; o >>= 1) lmax = fmaxf(lmax, __shfl_xor_sync(~0u, lmax, o));
    if ((tid & 31) == 0) red[tid >> 5] = lmax;
    __syncthreads();
    if (tid == 0) { float mx = red[0]; for (int w = 1; w < 8; w++) mx = fmaxf(mx, red[w]); red[0] = mx; }
    __syncthreads();
    float mx = red[0];
    __syncthreads();
    float lsum = 0.f;
    for (int m = tid; m < NN; m += 256) { float e = expf(row[m] - mx); row[m] = e; lsum += e; }
#pragma unroll
    for (int o = 16; o; o >>= 1) lsum += __shfl_xor_sync(~0u, lsum, o);
    if ((tid & 31) == 0) red[tid >> 5] = lsum;
    __syncthreads();
    if (tid == 0) { float s = 0.f; for (int w = 0; w < 8; w++) s += red[w]; ssum = s; }
    __syncthreads();
    float inv = 1.f / ssum;
    for (int m = tid; m < NP; m += 256) {
        float v = (m < NN) ? row[m] * inv : 0.f;
        bf16 h, l; bsplit(v, h, l);
        Ahi[n * NP + m] = h; Alo[n * NP + m] = l;
    }
}

__global__ void k_srcsplit(const float* __restrict__ src, bf16* __restrict__ hi,
                           bf16* __restrict__ lo) {
    int idx = blockIdx.x * 256 + threadIdx.x;
    if (idx >= NP * NC0) return;
    int n = idx / NC0, col = idx % NC0, t = col >> 6, b = col & 63;
    float v = (n < NN) ? src[((size_t)b * TT + t) * NN + n] : 0.f;
    bf16 h, l; bsplit(v, h, l);
    hi[idx] = h; lo[idx] = l;
}

__global__ void k_nodew(const float* __restrict__ E, const float* __restrict__ pool,
                        float* __restrict__ out, int RC) {
    long idx = (long)blockIdx.x * 256 + threadIdx.x;
    if (idx >= (long)NN * RC) return;
    int n = (int)(idx / RC), rem = (int)(idx % RC);
    float s = 0.f;
#pragma unroll
    for (int d = 0; d < EMBD; d++) s = fmaf(E[n * EMBD + d], pool[(long)d * RC + rem], s);
    out[idx] = s;
}

__global__ void k_zeroH(float* H, bf16* Hhi, bf16* Hlo) {
    int i = blockIdx.x * 256 + threadIdx.x;
    if (i >= NN * NB) return;
    H[i] = 0.f; Hhi[i] = __float2bfloat16(0.f); Hlo[i] = __float2bfloat16(0.f);
}

// C[896,NCc] = (Ahi+Alo)[896,896] @ (Xhi+Xlo)[896,NCc], split-bf16 3-mma
__global__ void __launch_bounds__(256) k_mma(const bf16* __restrict__ Ahi,
                                             const bf16* __restrict__ Alo,
                                             const bf16* __restrict__ Xhi,
                                             const bf16* __restrict__ Xlo,
                                             float* __restrict__ C, int NCc) {
    __shared__ bf16 sAh[2][128 * 16], sAl[2][128 * 16];
    __shared__ bf16 sXh[2][16 * 128], sXl[2][16 * 128];
    const int tid = threadIdx.x, lane = tid & 31, warp = tid >> 5;
    const int wm = warp & 1, wn = warp >> 1;
    const int rowBase = blockIdx.y * 128, colBase = blockIdx.x * 128;
    const int ar = tid >> 1, ac = (tid & 1) * 8;
    const int xr = tid >> 4, xcc = tid & 15;
    const int xdst = xr * 128 + ((xcc ^ xr) & 15) * 8;

    float acc[4][4][4];
#pragma unroll
    for (int i = 0; i < 4; i++)
#pragma unroll
        for (int j = 0; j < 4; j++)
#pragma unroll
            for (int q = 0; q < 4; q++) acc[i][j][q] = 0.f;

    cp16(&sAh[0][ar * 16 + ac], Ahi + (size_t)(rowBase + ar) * NP + ac);
    cp16(&sAl[0][ar * 16 + ac], Alo + (size_t)(rowBase + ar) * NP + ac);
    cp16(&sXh[0][xdst], Xhi + (size_t)xr * NCc + colBase + xcc * 8);
    cp16(&sXl[0][xdst], Xlo + (size_t)xr * NCc + colBase + xcc * 8);
    asm volatile("cp.async.commit_group;");

    const int aoff = (lane & 15) * 32 + (lane >> 4) * 16;  // bytes
    const int bk = lane & 15, bch = lane >> 4;

#pragma unroll 1
    for (int kt = 0; kt < 56; ++kt) {
        if (kt < 55) {
            int k0 = (kt + 1) * 16, buf = (kt + 1) & 1;
            cp16(&sAh[buf][ar * 16 + ac], Ahi + (size_t)(rowBase + ar) * NP + k0 + ac);
            cp16(&sAl[buf][ar * 16 + ac], Alo + (size_t)(rowBase + ar) * NP + k0 + ac);
            cp16(&sXh[buf][xdst], Xhi + (size_t)(k0 + xr) * NCc + colBase + xcc * 8);
            cp16(&sXl[buf][xdst], Xlo + (size_t)(k0 + xr) * NCc + colBase + xcc * 8);
            asm volatile("cp.async.commit_group;");
            asm volatile("cp.async.wait_group 1;");
        } else {
            asm volatile("cp.async.wait_group 0;");
        }
        __syncthreads();
        int buf = kt & 1;
        unsigned bAh = (unsigned)__cvta_generic_to_shared(&sAh[buf][0]);
        unsigned bAl = (unsigned)__cvta_generic_to_shared(&sAl[buf][0]);
        unsigned bXh = (unsigned)__cvta_generic_to_shared(&sXh[buf][0]);
        unsigned bXl = (unsigned)__cvta_generic_to_shared(&sXl[buf][0]);

        unsigned ah[4][4], al[4][4], bh[2][4], bl[2][4];
#pragma unroll
        for (int i = 0; i < 4; i++) {
            int m0 = wm * 64 + i * 16;
            ldsm4(ah[i], bAh + m0 * 32 + aoff);
            ldsm4(al[i], bAl + m0 * 32 + aoff);
        }
#pragma unroll
        for (int j = 0; j < 2; j++) {
            int c = wn * 4 + j * 2 + bch;
            int cp = c ^ bk;
            ldsm4t(bh[j], bXh + bk * 256 + cp * 16);
            ldsm4t(bl[j], bXl + bk * 256 + cp * 16);
        }
#pragma unroll
        for (int i = 0; i < 4; i++)
#pragma unroll
            for (int j = 0; j < 2; j++)
#pragma unroll
                for (int h = 0; h < 2; h++) {
                    unsigned bph[2] = {bh[j][h * 2], bh[j][h * 2 + 1]};
                    unsigned bpl[2] = {bl[j][h * 2], bl[j][h * 2 + 1]};
                    float* cc = acc[i][j * 2 + h];
                    mma16816(cc, ah[i], bph);
                    mma16816(cc, ah[i], bpl);
                    mma16816(cc, al[i], bph);
                }
        __syncthreads();
    }
#pragma unroll
    for (int i = 0; i < 4; i++) {
        int r0 = rowBase + wm * 64 + i * 16 + (lane >> 2);
#pragma unroll
        for (int jn = 0; jn < 4; jn++) {
            int c0 = colBase + wn * 32 + jn * 8 + (lane & 3) * 2;
            *(float2*)&C[(size_t)r0 * NCc + c0] = make_float2(acc[i][jn][0], acc[i][jn][1]);
            *(float2*)&C[(size_t)(r0 + 8) * NCc + c0] = make_float2(acc[i][jn][2], acc[i][jn][3]);
        }
    }
}

// per-node gate GEMM [64 x Kd]@[Kd x 128] + sigmoid; writes z*h (fp32+bf16) and r
template <int XW>
__global__ void __launch_bounds__(256) k_gate(
    const float* __restrict__ X, long xsn, long xsb,
    const float* __restrict__ AX, long axsn, long axsb,
    const float* __restrict__ H, const float* __restrict__ AH,
    const float* __restrict__ W, const float* __restrict__ Bia,
    float* __restrict__ R, float* __restrict__ ZH,
    bf16* __restrict__ ZHhi, bf16* __restrict__ ZHlo) {
    constexpr int Kd = 2 * XW + 128;
    const int n = blockIdx.x, tid = threadIdx.x;
    __shared__ float Xs[16][64];
    __shared__ float Ws[16][128];
    const int rg = tid >> 4, cg = tid & 15;
    float acc[4][8];
#pragma unroll
    for (int i = 0; i < 4; i++)
#pragma unroll
        for (int j = 0; j < 8; j++) acc[i][j] = 0.f;
    const float* Wn = W + (size_t)n * Kd * 128;

    for (int k0 = 0; k0 < Kd; k0 += 16) {
#pragma unroll
        for (int i = 0; i < 4; i++) {
            int idx = tid * 4 + i, b = idx >> 4, c = idx & 15, kk = k0 + c;
            float v = 0.f;
            if (kk < Kd) {
                if (kk < XW) v = X[(size_t)n * xsn + (size_t)b * xsb + kk];
                else if (kk < XW + 64) v = H[(size_t)n * NB + b * 64 + kk - XW];
                else if (kk < 2 * XW + 64) v = AX[(size_t)n * axsn + (size_t)b * axsb + kk - XW - 64];
                else v = AH[(size_t)n * NB + b * 64 + kk - 2 * XW - 64];
            }
            Xs[c][b] = v;
        }
#pragma unroll
        for (int i = 0; i < 8; i++) {
            int idx = tid + i * 256, r = idx >> 7, c = idx & 127, kk = k0 + r;
            Ws[r][c] = (kk < Kd) ? Wn[(size_t)kk * 128 + c] : 0.f;
        }
        __syncthreads();
#pragma unroll
        for (int k = 0; k < 16; k++) {
            float4 av = *(const float4*)&Xs[k][rg * 4];
            float a[4] = {av.x, av.y, av.z, av.w};
            float bb[8];
#pragma unroll
            for (int j = 0; j < 8; j++) bb[j] = Ws[k][cg * 8 + j];
#pragma unroll
            for (int i = 0; i < 4; i++)
#pragma unroll
                for (int j = 0; j < 8; j++) acc[i][j] = fmaf(a[i], bb[j], acc[i][j]);
        }
        __syncthreads();
    }
#pragma unroll
    for (int i = 0; i < 4; i++) {
        int b = rg * 4 + i;
        size_t base = (size_t)n * NB + b * 64;
#pragma unroll
        for (int j = 0; j < 8; j++) {
            int o = cg * 8 + j;
            float s = 1.f / (1.f + expf(-(acc[i][j] + Bia[n * 128 + o])));
            if (o < 64) {
                float zh = s * H[base + o];
                ZH[base + o] = zh;
                bf16 h, l; bsplit(zh, h, l);
                ZHhi[base + o] = h; ZHlo[base + o] = l;
            } else {
                R[base + o - 64] = s;
            }
        }
    }
}

// per-node candidate GEMM + tanh + GRU update
template <int XW>
__global__ void __launch_bounds__(256) k_cand(
    const float* __restrict__ X, long xsn, long xsb,
    const float* __restrict__ AX, long axsn, long axsb,
    const float* __restrict__ ZH, const float* __restrict__ AZH,
    const float* __restrict__ W, const float* __restrict__ Bia,
    const float* __restrict__ R, float* __restrict__ H,
    bf16* __restrict__ Hhi, bf16* __restrict__ Hlo,
    float* __restrict__ SEQ, bf16* __restrict__ Shi, bf16* __restrict__ Slo,
    long seqOff) {
    constexpr int Kd = 2 * XW + 128;
    const int n = blockIdx.x, tid = threadIdx.x;
    __shared__ float Xs[16][64];
    __shared__ float Ws[16][64];
    const int rg = tid >> 4, cg = tid & 15;
    float acc[4][4];
#pragma unroll
    for (int i = 0; i < 4; i++)
#pragma unroll
        for (int j = 0; j < 4; j++) acc[i][j] = 0.f;
    const float* Wn = W + (size_t)n * Kd * 64;

    for (int k0 = 0; k0 < Kd; k0 += 16) {
#pragma unroll
        for (int i = 0; i < 4; i++) {
            int idx = tid * 4 + i, b = idx >> 4, c = idx & 15, kk = k0 + c;
            float v = 0.f;
            if (kk < Kd) {
                if (kk < XW) v = X[(size_t)n * xsn + (size_t)b * xsb + kk];
                else if (kk < XW + 64) v = ZH[(size_t)n * NB + b * 64 + kk - XW];
                else if (kk < 2 * XW + 64) v = AX[(size_t)n * axsn + (size_t)b * axsb + kk - XW - 64];
                else v = AZH[(size_t)n * NB + b * 64 + kk - 2 * XW - 64];
            }
            Xs[c][b] = v;
        }
#pragma unroll
        for (int i = 0; i < 4; i++) {
            int idx = tid + i * 256, r = idx >> 6, c = idx & 63, kk = k0 + r;
            Ws[r][c] = (kk < Kd) ? Wn[(size_t)kk * 64 + c] : 0.f;
        }
        __syncthreads();
#pragma unroll
        for (int k = 0; k < 16; k++) {
            float4 av = *(const float4*)&Xs[k][rg * 4];
            float a[4] = {av.x, av.y, av.z, av.w};
            float bb[4];
#pragma unroll
            for (int j = 0; j < 4; j++) bb[j] = Ws[k][cg * 4 + j];
#pragma unroll
            for (int i = 0; i < 4; i++)
#pragma unroll
                for (int j = 0; j < 4; j++) acc[i][j] = fmaf(a[i], bb[j], acc[i][j]);
        }
        __syncthreads();
    }
#pragma unroll
    for (int i = 0; i < 4; i++) {
        int b = rg * 4 + i;
        size_t base = (size_t)n * NB + b * 64;
#pragma unroll
        for (int j = 0; j < 4; j++) {
            int o = cg * 4 + j;
            float hc = tanhf(acc[i][j] + Bia[n * 64 + o]);
            float r = R[base + o];
            float hn = r * H[base + o] + (1.f - r) * hc;
            H[base + o] = hn;
            bf16 bh, bl; bsplit(hn, bh, bl);
            Hhi[base + o] = bh; Hlo[base + o] = bl;
            if (SEQ) {
                size_t s = (size_t)n * NCSEQ + seqOff + b * 64 + o;
                SEQ[s] = hn; Shi[s] = bh; Slo[s] = bl;
            }
        }
    }
}

__global__ void k_final(const float* __restrict__ H, const float* __restrict__ cw,
                        const float* __restrict__ cb, float* __restrict__ out) {
    int idx = blockIdx.x * 256 + threadIdx.x;
    if (idx >= BB * NN) return;
    int n = idx % NN, b = idx / NN;
    const float* h = H + (size_t)n * NB + b * 64;
    float hv[HID];
#pragma unroll
    for (int j = 0; j < HID; j++) hv[j] = h[j];
#pragma unroll
    for (int o = 0; o < TT; o++) {
        float s = cb[o];
#pragma unroll
        for (int j = 0; j < HID; j++) s = fmaf(hv[j], cw[o * HID + j], s);
        out[((size_t)b * TT + o) * NN + n] = s;
    }
}

extern "C" void kernel_launch(void* const* d_in, const int* in_sizes, int n_in,
                              void* d_out, int out_size) {
    const float* src = (const float*)d_in[0];
    const float* E = (const float*)d_in[1];
    const float* pw[8] = {(const float*)d_in[2], (const float*)d_in[3],
                          (const float*)d_in[4], (const float*)d_in[5],
                          (const float*)d_in[6], (const float*)d_in[7],
                          (const float*)d_in[8], (const float*)d_in[9]};
    const float* cw = (const float*)d_in[10];
    const float* cb = (const float*)d_in[11];
    float* out = (float*)d_out;

    bf16 *Ahi, *Alo, *Hhi, *Hlo, *ZHhi, *ZHlo, *Shi, *Slo, *X0hi, *X0lo;
    float *Wg0, *Wc0, *Wg1, *Wc1, *Bg0, *Bc0, *Bg1, *Bc1;
    float *H, *ZH, *R, *AH, *AZH, *SEQ, *ASEQ, *AX0;
    cudaGetSymbolAddress((void**)&Ahi, g_Ahi);
    cudaGetSymbolAddress((void**)&Alo, g_Alo);
    cudaGetSymbolAddress((void**)&Wg0, g_Wg0);
    cudaGetSymbolAddress((void**)&Wc0, g_Wc0);
    cudaGetSymbolAddress((void**)&Wg1, g_Wg1);
    cudaGetSymbolAddress((void**)&Wc1, g_Wc1);
    cudaGetSymbolAddress((void**)&Bg0, g_Bg0);
    cudaGetSymbolAddress((void**)&Bc0, g_Bc0);
    cudaGetSymbolAddress((void**)&Bg1, g_Bg1);
    cudaGetSymbolAddress((void**)&Bc1, g_Bc1);
    cudaGetSymbolAddress((void**)&H, g_H);
    cudaGetSymbolAddress((void**)&Hhi, g_Hhi);
    cudaGetSymbolAddress((void**)&Hlo, g_Hlo);
    cudaGetSymbolAddress((void**)&ZH, g_ZH);
    cudaGetSymbolAddress((void**)&ZHhi, g_ZHhi);
    cudaGetSymbolAddress((void**)&ZHlo, g_ZHlo);
    cudaGetSymbolAddress((void**)&R, g_R);
    cudaGetSymbolAddress((void**)&AH, g_AH);
    cudaGetSymbolAddress((void**)&AZH, g_AZH);
    cudaGetSymbolAddress((void**)&SEQ, g_SEQ);
    cudaGetSymbolAddress((void**)&Shi, g_SEQhi);
    cudaGetSymbolAddress((void**)&Slo, g_SEQlo);
    cudaGetSymbolAddress((void**)&ASEQ, g_ASEQ);
    cudaGetSymbolAddress((void**)&X0hi, g_X0hi);
    cudaGetSymbolAddress((void**)&X0lo, g_X0lo);
    cudaGetSymbolAddress((void**)&AX0, g_AX0);

    k_supports<<<NP, 256>>>(E, Ahi, Alo);
    k_srcsplit<<<(NP * NC0 + 255) / 256, 256>>>(src, X0hi, X0lo);
    k_nodew<<<((long)NN * 130 * 128 + 255) / 256, 256>>>(E, pw[0], Wg0, 130 * 128);
    k_nodew<<<((long)NN * 128 + 255) / 256, 256>>>(E, pw[1], Bg0, 128);
    k_nodew<<<((long)NN * 130 * 64 + 255) / 256, 256>>>(E, pw[2], Wc0, 130 * 64);
    k_nodew<<<((long)NN * 64 + 255) / 256, 256>>>(E, pw[3], Bc0, 64);
    k_nodew<<<((long)NN * 256 * 128 + 255) / 256, 256>>>(E, pw[4], Wg1, 256 * 128);
    k_nodew<<<((long)NN * 128 + 255) / 256, 256>>>(E, pw[5], Bg1, 128);
    k_nodew<<<((long)NN * 256 * 64 + 255) / 256, 256>>>(E, pw[6], Wc1, 256 * 64);
    k_nodew<<<((long)NN * 64 + 255) / 256, 256>>>(E, pw[7], Bc1, 64);

    k_mma<<<dim3(NC0 / 128, 7), 256>>>(Ahi, Alo, X0hi, X0lo, AX0, NC0);

    // layer 0
    k_zeroH<<<(NN * NB + 255) / 256, 256>>>(H, Hhi, Hlo);
    for (int t = 0; t < TT; t++) {
        k_mma<<<dim3(NB / 128, 7), 256>>>(Ahi, Alo, Hhi, Hlo, AH, NB);
        k_gate<1><<<NN, 256>>>(src + (size_t)t * NN, 1L, (long)TT * NN,
                               AX0 + t * 64, (long)NC0, 1L, H, AH, Wg0, Bg0,
                               R, ZH, ZHhi, ZHlo);
        k_mma<<<dim3(NB / 128, 7), 256>>>(Ahi, Alo, ZHhi, ZHlo, AZH, NB);
        k_cand<1><<<NN, 256>>>(src + (size_t)t * NN, 1L, (long)TT * NN,
                               AX0 + t * 64, (long)NC0, 1L, ZH, AZH, Wc0, Bc0,
                               R, H, Hhi, Hlo, SEQ, Shi, Slo, (long)t * NB);
    }

    k_mma<<<dim3(NCSEQ / 128, 7), 256>>>(Ahi, Alo, Shi, Slo, ASEQ, NCSEQ);

    // layer 1
    k_zeroH<<<(NN * NB + 255) / 256, 256>>>(H, Hhi, Hlo);
    for (int t = 0; t < TT; t++) {
        k_mma<<<dim3(NB / 128, 7), 256>>>(Ahi, Alo, Hhi, Hlo, AH, NB);
        k_gate<64><<<NN, 256>>>(SEQ + (size_t)t * NB, (long)NCSEQ, 64L,
                                ASEQ + (size_t)t * NB, (long)NCSEQ, 64L, H, AH,
                                Wg1, Bg1, R, ZH, ZHhi, ZHlo);
        k_mma<<<dim3(NB / 128, 7), 256>>>(Ahi, Alo, ZHhi, ZHlo, AZH, NB);
        k_cand<64><<<NN, 256>>>(SEQ + (size_t)t * NB, (long)NCSEQ, 64L,
                                ASEQ + (size_t)t * NB, (long)NCSEQ, 64L, ZH, AZH,
                                Wc1, Bc1, R, H, Hhi, Hlo,
                                (float*)0, (bf16*)0, (bf16*)0, 0L);
    }

    k_final<<<(BB * NN + 255) / 256, 256>>>(H, cw, cb, out);
}

// round 4
// speedup vs baseline: 3.4259x; 1.5935x over previous
#include <cuda_runtime.h>
#include <cuda_bf16.h>
#include <math.h>

#define NN 883
#define NP 896
#define BB 64
#define TT 12
#define HID 64
#define EMBD 10
#define NB 4096
#define NCSEQ 49152
#define NC0 768
typedef __nv_bfloat16 bf16;

// ---------------- device scratch ----------------
__device__ bf16 g_Ahi[NP * NP];
__device__ bf16 g_Alo[NP * NP];
__device__ bf16 g_X0hi[NP * NC0];
__device__ bf16 g_X0lo[NP * NC0];
__device__ bf16 g_AX0hi[NP * NC0];
__device__ bf16 g_AX0lo[NP * NC0];
__device__ bf16 g_WG0h[NN * 144 * 128];
__device__ bf16 g_WG0l[NN * 144 * 128];
__device__ bf16 g_WC0h[NN * 144 * 64];
__device__ bf16 g_WC0l[NN * 144 * 64];
__device__ bf16 g_WG1h[NN * 256 * 128];
__device__ bf16 g_WG1l[NN * 256 * 128];
__device__ bf16 g_WC1h[NN * 256 * 64];
__device__ bf16 g_WC1l[NN * 256 * 64];
__device__ float g_Bg0[NN * 128];
__device__ float g_Bc0[NN * 64];
__device__ float g_Bg1[NN * 128];
__device__ float g_Bc1[NN * 64];
__device__ float g_H[NN * NB];
__device__ float g_R[NN * NB];
__device__ bf16 g_Hhi[NP * NB];
__device__ bf16 g_Hlo[NP * NB];
__device__ bf16 g_ZHhi[NP * NB];
__device__ bf16 g_ZHlo[NP * NB];
__device__ bf16 g_AHhi[NP * NB];
__device__ bf16 g_AHlo[NP * NB];
__device__ bf16 g_AZHhi[NP * NB];
__device__ bf16 g_AZHlo[NP * NB];
__device__ bf16 g_SEQhi[(size_t)NP * NCSEQ];
__device__ bf16 g_SEQlo[(size_t)NP * NCSEQ];
__device__ bf16 g_ASEQhi[(size_t)NP * NCSEQ];
__device__ bf16 g_ASEQlo[(size_t)NP * NCSEQ];

__device__ __forceinline__ void bsplit(float v, bf16& hi, bf16& lo) {
    hi = __float2bfloat16_rn(v);
    lo = __float2bfloat16_rn(v - __bfloat162float(hi));
}
__device__ __forceinline__ void cp16(void* s, const void* g) {
    unsigned sa = (unsigned)__cvta_generic_to_shared(s);
    asm volatile("cp.async.cg.shared.global [%0], [%1], 16;" :: "r"(sa), "l"(g));
}
__device__ __forceinline__ void ldsm4(unsigned* r, unsigned a) {
    asm volatile("ldmatrix.sync.aligned.m8n8.x4.shared.b16 {%0,%1,%2,%3}, [%4];"
                 : "=r"(r[0]), "=r"(r[1]), "=r"(r[2]), "=r"(r[3]) : "r"(a));
}
__device__ __forceinline__ void ldsm4t(unsigned* r, unsigned a) {
    asm volatile("ldmatrix.sync.aligned.m8n8.x4.trans.shared.b16 {%0,%1,%2,%3}, [%4];"
                 : "=r"(r[0]), "=r"(r[1]), "=r"(r[2]), "=r"(r[3]) : "r"(a));
}
__device__ __forceinline__ void mma16816(float* c, const unsigned* a, const unsigned* b) {
    asm volatile(
        "mma.sync.aligned.m16n8k16.row.col.f32.bf16.bf16.f32 "
        "{%0,%1,%2,%3},{%4,%5,%6,%7},{%8,%9},{%0,%1,%2,%3};"
        : "+f"(c[0]), "+f"(c[1]), "+f"(c[2]), "+f"(c[3])
        : "r"(a[0]), "r"(a[1]), "r"(a[2]), "r"(a[3]), "r"(b[0]), "r"(b[1]));
}
__device__ __forceinline__ void st2(bf16* p, bf16 a, bf16 b) {
    __nv_bfloat162 v; v.x = a; v.y = b;
    *(__nv_bfloat162*)p = v;
}

// ---------------- adjacency ----------------
__global__ void __launch_bounds__(256) k_supports(const float* __restrict__ E,
                                                  bf16* __restrict__ Ahi,
                                                  bf16* __restrict__ Alo) {
    int n = blockIdx.x, tid = threadIdx.x;
    if (n >= NN) {
        for (int m = tid; m < NP; m += 256) { Ahi[n * NP + m] = __float2bfloat16(0.f); Alo[n * NP + m] = __float2bfloat16(0.f); }
        return;
    }
    __shared__ float row[NN];
    __shared__ float red[8];
    __shared__ float ssum;
    float en[EMBD];
#pragma unroll
    for (int d = 0; d < EMBD; d++) en[d] = E[n * EMBD + d];
    float lmax = -1e30f;
    for (int m = tid; m < NN; m += 256) {
        float s = 0.f;
#pragma unroll
        for (int d = 0; d < EMBD; d++) s = fmaf(en[d], E[m * EMBD + d], s);
        s = fmaxf(s, 0.f);
        row[m] = s;
        lmax = fmaxf(lmax, s);
    }
#pragma unroll
    for (int o = 16; o; o >>= 1) lmax = fmaxf(lmax, __shfl_xor_sync(~0u, lmax, o));
    if ((tid & 31) == 0) red[tid >> 5] = lmax;
    __syncthreads();
    if (tid == 0) { float mx = red[0]; for (int w = 1; w < 8; w++) mx = fmaxf(mx, red[w]); red[0] = mx; }
    __syncthreads();
    float mx = red[0];
    __syncthreads();
    float lsum = 0.f;
    for (int m = tid; m < NN; m += 256) { float e = expf(row[m] - mx); row[m] = e; lsum += e; }
#pragma unroll
    for (int o = 16; o; o >>= 1) lsum += __shfl_xor_sync(~0u, lsum, o);
    if ((tid & 31) == 0) red[tid >> 5] = lsum;
    __syncthreads();
    if (tid == 0) { float s = 0.f; for (int w = 0; w < 8; w++) s += red[w]; ssum = s; }
    __syncthreads();
    float inv = 1.f / ssum;
    for (int m = tid; m < NP; m += 256) {
        float v = (m < NN) ? row[m] * inv : 0.f;
        bf16 h, l; bsplit(v, h, l);
        Ahi[n * NP + m] = h; Alo[n * NP + m] = l;
    }
}

__global__ void k_srcsplit(const float* __restrict__ src, bf16* __restrict__ hi,
                           bf16* __restrict__ lo) {
    int idx = blockIdx.x * 256 + threadIdx.x;
    if (idx >= NP * NC0) return;
    int n = idx / NC0, col = idx % NC0, t = col >> 6, b = col & 63;
    float v = (n < NN) ? src[((size_t)b * TT + t) * NN + n] : 0.f;
    bf16 h, l; bsplit(v, h, l);
    hi[idx] = h; lo[idx] = l;
}

// pooled per-node weights -> bf16 splits with K-layout permutation
__global__ void k_nodewsplit(const float* __restrict__ E, const float* __restrict__ pool,
                             bf16* __restrict__ Whi, bf16* __restrict__ Wlo,
                             int COUT, int KDp, int layer) {
    long idx = (long)blockIdx.x * 256 + threadIdx.x;
    if (idx >= (long)NN * KDp * COUT) return;
    int o = (int)(idx % COUT);
    long r2 = idx / COUT;
    int k = (int)(r2 % KDp);
    int n = (int)(r2 / KDp);
    int row, ROWS;
    if (layer == 0) {
        ROWS = 130;
        if (k < 64) row = k + 1;
        else if (k < 128) row = k + 2;
        else if (k == 128) row = 0;
        else if (k == 129) row = 65;
        else row = -1;
    } else { ROWS = 256; row = k; }
    float s = 0.f;
    if (row >= 0)
#pragma unroll
        for (int d = 0; d < EMBD; d++)
            s = fmaf(E[n * EMBD + d], pool[((long)d * ROWS + row) * COUT + o], s);
    bf16 h, l; bsplit(s, h, l);
    Whi[idx] = h; Wlo[idx] = l;
}

__global__ void k_nodew(const float* __restrict__ E, const float* __restrict__ pool,
                        float* __restrict__ out, int RC) {
    long idx = (long)blockIdx.x * 256 + threadIdx.x;
    if (idx >= (long)NN * RC) return;
    int n = (int)(idx / RC), rem = (int)(idx % RC);
    float s = 0.f;
#pragma unroll
    for (int d = 0; d < EMBD; d++) s = fmaf(E[n * EMBD + d], pool[(long)d * RC + rem], s);
    out[idx] = s;
}

__global__ void k_zeroH(float* H, bf16* Hhi, bf16* Hlo) {
    int i = blockIdx.x * 256 + threadIdx.x;
    if (i >= NN * NB) return;
    H[i] = 0.f; Hhi[i] = __float2bfloat16(0.f); Hlo[i] = __float2bfloat16(0.f);
}

// ---------------- dense split-bf16 MMA: C(hi,lo) = A @ X ----------------
__global__ void __launch_bounds__(256) k_mma(const bf16* __restrict__ Ahi,
                                             const bf16* __restrict__ Alo,
                                             const bf16* __restrict__ Xhi,
                                             const bf16* __restrict__ Xlo,
                                             bf16* __restrict__ Chi,
                                             bf16* __restrict__ Clo, int NCc) {
    __shared__ bf16 sAh[2][128 * 16], sAl[2][128 * 16];
    __shared__ bf16 sXh[2][16 * 128], sXl[2][16 * 128];
    const int tid = threadIdx.x, lane = tid & 31, warp = tid >> 5;
    const int wm = warp & 1, wn = warp >> 1;
    const int rowBase = blockIdx.y * 128, colBase = blockIdx.x * 128;
    const int ar = tid >> 1, ac = (tid & 1) * 8;
    const int xr = tid >> 4, xcc = tid & 15;
    const int xdst = xr * 128 + ((xcc ^ xr) & 15) * 8;

    float acc[4][4][4];
#pragma unroll
    for (int i = 0; i < 4; i++)
#pragma unroll
        for (int j = 0; j < 4; j++)
#pragma unroll
            for (int q = 0; q < 4; q++) acc[i][j][q] = 0.f;

    cp16(&sAh[0][ar * 16 + ac], Ahi + (size_t)(rowBase + ar) * NP + ac);
    cp16(&sAl[0][ar * 16 + ac], Alo + (size_t)(rowBase + ar) * NP + ac);
    cp16(&sXh[0][xdst], Xhi + (size_t)xr * NCc + colBase + xcc * 8);
    cp16(&sXl[0][xdst], Xlo + (size_t)xr * NCc + colBase + xcc * 8);
    asm volatile("cp.async.commit_group;");

    const int aoff = (lane & 15) * 32 + (lane >> 4) * 16;
    const int bk = lane & 15, bch = lane >> 4;

#pragma unroll 1
    for (int kt = 0; kt < 56; ++kt) {
        if (kt < 55) {
            int k0 = (kt + 1) * 16, buf = (kt + 1) & 1;
            cp16(&sAh[buf][ar * 16 + ac], Ahi + (size_t)(rowBase + ar) * NP + k0 + ac);
            cp16(&sAl[buf][ar * 16 + ac], Alo + (size_t)(rowBase + ar) * NP + k0 + ac);
            cp16(&sXh[buf][xdst], Xhi + (size_t)(k0 + xr) * NCc + colBase + xcc * 8);
            cp16(&sXl[buf][xdst], Xlo + (size_t)(k0 + xr) * NCc + colBase + xcc * 8);
            asm volatile("cp.async.commit_group;");
            asm volatile("cp.async.wait_group 1;");
        } else {
            asm volatile("cp.async.wait_group 0;");
        }
        __syncthreads();
        int buf = kt & 1;
        unsigned bAh = (unsigned)__cvta_generic_to_shared(&sAh[buf][0]);
        unsigned bAl = (unsigned)__cvta_generic_to_shared(&sAl[buf][0]);
        unsigned bXh = (unsigned)__cvta_generic_to_shared(&sXh[buf][0]);
        unsigned bXl = (unsigned)__cvta_generic_to_shared(&sXl[buf][0]);
        unsigned ah[4][4], al[4][4], bh[2][4], bl[2][4];
#pragma unroll
        for (int i = 0; i < 4; i++) {
            int m0 = wm * 64 + i * 16;
            ldsm4(ah[i], bAh + m0 * 32 + aoff);
            ldsm4(al[i], bAl + m0 * 32 + aoff);
        }
#pragma unroll
        for (int j = 0; j < 2; j++) {
            int c = wn * 4 + j * 2 + bch;
            int cp = c ^ bk;
            ldsm4t(bh[j], bXh + bk * 256 + cp * 16);
            ldsm4t(bl[j], bXl + bk * 256 + cp * 16);
        }
#pragma unroll
        for (int i = 0; i < 4; i++)
#pragma unroll
            for (int j = 0; j < 2; j++)
#pragma unroll
                for (int h = 0; h < 2; h++) {
                    unsigned bph[2] = {bh[j][h * 2], bh[j][h * 2 + 1]};
                    unsigned bpl[2] = {bl[j][h * 2], bl[j][h * 2 + 1]};
                    float* cc = acc[i][j * 2 + h];
                    mma16816(cc, ah[i], bph);
                    mma16816(cc, ah[i], bpl);
                    mma16816(cc, al[i], bph);
                }
        __syncthreads();
    }
#pragma unroll
    for (int i = 0; i < 4; i++) {
        int r0 = rowBase + wm * 64 + i * 16 + (lane >> 2);
#pragma unroll
        for (int jn = 0; jn < 4; jn++) {
            int c0 = colBase + wn * 32 + jn * 8 + (lane & 3) * 2;
            bf16 h0, l0, h1, l1;
            bsplit(acc[i][jn][0], h0, l0); bsplit(acc[i][jn][1], h1, l1);
            st2(&Chi[(size_t)r0 * NCc + c0], h0, h1);
            st2(&Clo[(size_t)r0 * NCc + c0], l0, l1);
            bsplit(acc[i][jn][2], h0, l0); bsplit(acc[i][jn][3], h1, l1);
            st2(&Chi[(size_t)(r0 + 8) * NCc + c0], h0, h1);
            st2(&Clo[(size_t)(r0 + 8) * NCc + c0], l0, l1);
        }
    }
}

// ---------------- per-node tensor-core GEMM + fused epilogue ----------------
template <int COUT, bool CAND, bool L0>
__global__ void __launch_bounds__(128) k_pn(
    const bf16* __restrict__ xh, const bf16* __restrict__ xl, size_t xstr, size_t xoff,
    const bf16* __restrict__ hh, const bf16* __restrict__ hl,
    const bf16* __restrict__ axh, const bf16* __restrict__ axl, size_t axstr, size_t axoff,
    const bf16* __restrict__ ahh, const bf16* __restrict__ ahl,
    const bf16* __restrict__ Whi, const bf16* __restrict__ Wlo,
    const float* __restrict__ Bias, float* __restrict__ R, float* __restrict__ Hfp,
    bf16* __restrict__ o1h, bf16* __restrict__ o1l,
    bf16* __restrict__ s1h, bf16* __restrict__ s1l, size_t seqOff) {
    constexpr int NCH = L0 ? 9 : 16;
    constexpr int SLICE = COUT / 4;
    constexpr int NJ = SLICE / 16;      // 2 (gate) or 1 (cand)
    constexpr int WCH = COUT / 8;       // 16B chunks per W row
    __shared__ bf16 sXh[2][64 * 24], sXl[2][64 * 24];
    __shared__ bf16 sWh[2][16 * COUT], sWl[2][16 * COUT];
    const int n = blockIdx.x, tid = threadIdx.x, lane = tid & 31, wn = tid >> 5;
    const bf16* Wh = Whi + (size_t)n * NCH * 16 * COUT;
    const bf16* Wl = Wlo + (size_t)n * NCH * 16 * COUT;

    float acc[4][NJ * 2][4];
#pragma unroll
    for (int i = 0; i < 4; i++)
#pragma unroll
        for (int j = 0; j < NJ * 2; j++)
#pragma unroll
            for (int q = 0; q < 4; q++) acc[i][j][q] = 0.f;

    auto prefetch = [&](int c) {
        int buf = c & 1;
#pragma unroll
        for (int q = tid; q < 16 * WCH; q += 128) {
            int r = q / WCH, cc = q % WCH;
            int dst = r * COUT + (cc ^ (r & (WCH - 1))) * 8;
            size_t src = (size_t)(c * 16 + r) * COUT + cc * 8;
            cp16(&sWh[buf][dst], Wh + src);
            cp16(&sWl[buf][dst], Wl + src);
        }
        if (L0 && c == 8) {
            if (tid < 64) {
                int b = tid;
                bf16 z = __float2bfloat16(0.f);
#pragma unroll
                for (int k = 0; k < 16; k++) { sXh[buf][b * 24 + k] = z; sXl[buf][b * 24 + k] = z; }
                sXh[buf][b * 24 + 0] = xh[n * xstr + xoff + b];
                sXl[buf][b * 24 + 0] = xl[n * xstr + xoff + b];
                sXh[buf][b * 24 + 1] = axh[n * axstr + axoff + b];
                sXl[buf][b * 24 + 1] = axl[n * axstr + axoff + b];
            }
        } else {
            int b = tid >> 1, half = tid & 1;
            const bf16 *ph, *pl; size_t base;
            if (L0) {
                if (c < 4) { ph = hh; pl = hl; base = (size_t)n * NB + b * 64 + c * 16 + half * 8; }
                else { ph = ahh; pl = ahl; base = (size_t)n * NB + b * 64 + (c - 4) * 16 + half * 8; }
            } else {
                int g = c >> 2, kl = (c & 3) * 16 + half * 8;
                if (g == 0) { ph = xh; pl = xl; base = (size_t)n * xstr + xoff + b * 64 + kl; }
                else if (g == 1) { ph = hh; pl = hl; base = (size_t)n * NB + b * 64 + kl; }
                else if (g == 2) { ph = axh; pl = axl; base = (size_t)n * axstr + axoff + b * 64 + kl; }
                else { ph = ahh; pl = ahl; base = (size_t)n * NB + b * 64 + kl; }
            }
            cp16(&sXh[buf][b * 24 + half * 8], ph + base);
            cp16(&sXl[buf][b * 24 + half * 8], pl + base);
        }
        asm volatile("cp.async.commit_group;");
    };

    prefetch(0);
#pragma unroll 1
    for (int c = 0; c < NCH; c++) {
        if (c + 1 < NCH) { prefetch(c + 1); asm volatile("cp.async.wait_group 1;"); }
        else asm volatile("cp.async.wait_group 0;");
        __syncthreads();
        int buf = c & 1;
        unsigned bXh = (unsigned)__cvta_generic_to_shared(&sXh[buf][0]);
        unsigned bXl = (unsigned)__cvta_generic_to_shared(&sXl[buf][0]);
        unsigned bWh = (unsigned)__cvta_generic_to_shared(&sWh[buf][0]);
        unsigned bWl = (unsigned)__cvta_generic_to_shared(&sWl[buf][0]);
        unsigned ah[4][4], al[4][4], bh[NJ][4], bl[NJ][4];
#pragma unroll
        for (int i = 0; i < 4; i++) {
            unsigned off = (i * 16 + (lane & 15)) * 48 + (lane >> 4) * 16;
            ldsm4(ah[i], bXh + off);
            ldsm4(al[i], bXl + off);
        }
        int bk = lane & 15;
#pragma unroll
        for (int j = 0; j < NJ; j++) {
            int cch = wn * (SLICE / 8) + j * 2 + (lane >> 4);
            unsigned off = bk * (COUT * 2) + (cch ^ (bk & (WCH - 1))) * 16;
            ldsm4t(bh[j], bWh + off);
            ldsm4t(bl[j], bWl + off);
        }
#pragma unroll
        for (int i = 0; i < 4; i++)
#pragma unroll
            for (int j = 0; j < NJ; j++)
#pragma unroll
                for (int h = 0; h < 2; h++) {
                    unsigned bph[2] = {bh[j][h * 2], bh[j][h * 2 + 1]};
                    unsigned bpl[2] = {bl[j][h * 2], bl[j][h * 2 + 1]};
                    float* cc = acc[i][j * 2 + h];
                    mma16816(cc, ah[i], bph);
                    mma16816(cc, ah[i], bpl);
                    mma16816(cc, al[i], bph);
                }
        __syncthreads();
    }

#pragma unroll
    for (int i = 0; i < 4; i++) {
        int b0 = i * 16 + (lane >> 2);
#pragma unroll
        for (int jn = 0; jn < NJ * 2; jn++) {
            int o = wn * SLICE + jn * 8 + (lane & 3) * 2;
#pragma unroll
            for (int rr = 0; rr < 2; rr++) {
                int b = b0 + rr * 8;
                size_t ix = (size_t)n * NB + b * 64;
                float v0 = acc[i][jn][rr * 2 + 0] + Bias[n * COUT + o];
                float v1 = acc[i][jn][rr * 2 + 1] + Bias[n * COUT + o + 1];
                if (!CAND) {
                    float s0 = 1.f / (1.f + expf(-v0));
                    float s1 = 1.f / (1.f + expf(-v1));
                    if (o < 64) {
                        float z0 = s0 * Hfp[ix + o], z1 = s1 * Hfp[ix + o + 1];
                        bf16 h0, l0, h1, l1;
                        bsplit(z0, h0, l0); bsplit(z1, h1, l1);
                        st2(&o1h[ix + o], h0, h1);
                        st2(&o1l[ix + o], l0, l1);
                    } else {
                        R[ix + o - 64] = s0; R[ix + o - 63] = s1;
                    }
                } else {
                    float hc0 = tanhf(v0), hc1 = tanhf(v1);
                    float r0 = R[ix + o], r1 = R[ix + o + 1];
                    float hn0 = r0 * Hfp[ix + o] + (1.f - r0) * hc0;
                    float hn1 = r1 * Hfp[ix + o + 1] + (1.f - r1) * hc1;
                    Hfp[ix + o] = hn0; Hfp[ix + o + 1] = hn1;
                    bf16 h0, l0, h1, l1;
                    bsplit(hn0, h0, l0); bsplit(hn1, h1, l1);
                    st2(&o1h[ix + o], h0, h1);
                    st2(&o1l[ix + o], l0, l1);
                    if (s1h) {
                        size_t s = (size_t)n * NCSEQ + seqOff + b * 64 + o;
                        st2(&s1h[s], h0, h1);
                        st2(&s1l[s], l0, l1);
                    }
                }
            }
        }
    }
}

__global__ void k_final(const float* __restrict__ H, const float* __restrict__ cw,
                        const float* __restrict__ cb, float* __restrict__ out) {
    int idx = blockIdx.x * 256 + threadIdx.x;
    if (idx >= BB * NN) return;
    int n = idx % NN, b = idx / NN;
    const float* h = H + (size_t)n * NB + b * 64;
    float hv[HID];
#pragma unroll
    for (int j = 0; j < HID; j++) hv[j] = h[j];
#pragma unroll
    for (int o = 0; o < TT; o++) {
        float s = cb[o];
#pragma unroll
        for (int j = 0; j < HID; j++) s = fmaf(hv[j], cw[o * HID + j], s);
        out[((size_t)b * TT + o) * NN + n] = s;
    }
}

extern "C" void kernel_launch(void* const* d_in, const int* in_sizes, int n_in,
                              void* d_out, int out_size) {
    const float* src = (const float*)d_in[0];
    const float* E = (const float*)d_in[1];
    const float* cw = (const float*)d_in[10];
    const float* cb = (const float*)d_in[11];
    float* out = (float*)d_out;

#define SYM(T, v, s) T* v; cudaGetSymbolAddress((void**)&v, s)
    SYM(bf16, Ahi, g_Ahi); SYM(bf16, Alo, g_Alo);
    SYM(bf16, X0hi, g_X0hi); SYM(bf16, X0lo, g_X0lo);
    SYM(bf16, AX0hi, g_AX0hi); SYM(bf16, AX0lo, g_AX0lo);
    SYM(bf16, WG0h, g_WG0h); SYM(bf16, WG0l, g_WG0l);
    SYM(bf16, WC0h, g_WC0h); SYM(bf16, WC0l, g_WC0l);
    SYM(bf16, WG1h, g_WG1h); SYM(bf16, WG1l, g_WG1l);
    SYM(bf16, WC1h, g_WC1h); SYM(bf16, WC1l, g_WC1l);
    SYM(float, Bg0, g_Bg0); SYM(float, Bc0, g_Bc0);
    SYM(float, Bg1, g_Bg1); SYM(float, Bc1, g_Bc1);
    SYM(float, H, g_H); SYM(float, R, g_R);
    SYM(bf16, Hhi, g_Hhi); SYM(bf16, Hlo, g_Hlo);
    SYM(bf16, ZHhi, g_ZHhi); SYM(bf16, ZHlo, g_ZHlo);
    SYM(bf16, AHhi, g_AHhi); SYM(bf16, AHlo, g_AHlo);
    SYM(bf16, AZHhi, g_AZHhi); SYM(bf16, AZHlo, g_AZHlo);
    SYM(bf16, Shi, g_SEQhi); SYM(bf16, Slo, g_SEQlo);
    SYM(bf16, AShi, g_ASEQhi); SYM(bf16, ASlo, g_ASEQlo);

    k_supports<<<NP, 256>>>(E, Ahi, Alo);
    k_srcsplit<<<(NP * NC0 + 255) / 256, 256>>>(src, X0hi, X0lo);
    k_nodewsplit<<<(int)(((long)NN * 144 * 128 + 255) / 256), 256>>>(E, (const float*)d_in[2], WG0h, WG0l, 128, 144, 0);
    k_nodew<<<((long)NN * 128 + 255) / 256, 256>>>(E, (const float*)d_in[3], Bg0, 128);
    k_nodewsplit<<<(int)(((long)NN * 144 * 64 + 255) / 256), 256>>>(E, (const float*)d_in[4], WC0h, WC0l, 64, 144, 0);
    k_nodew<<<((long)NN * 64 + 255) / 256, 256>>>(E, (const float*)d_in[5], Bc0, 64);
    k_nodewsplit<<<(int)(((long)NN * 256 * 128 + 255) / 256), 256>>>(E, (const float*)d_in[6], WG1h, WG1l, 128, 256, 1);
    k_nodew<<<((long)NN * 128 + 255) / 256, 256>>>(E, (const float*)d_in[7], Bg1, 128);
    k_nodewsplit<<<(int)(((long)NN * 256 * 64 + 255) / 256), 256>>>(E, (const float*)d_in[8], WC1h, WC1l, 64, 256, 1);
    k_nodew<<<((long)NN * 64 + 255) / 256, 256>>>(E, (const float*)d_in[9], Bc1, 64);

    k_mma<<<dim3(NC0 / 128, 7), 256>>>(Ahi, Alo, X0hi, X0lo, AX0hi, AX0lo, NC0);

    // layer 0
    k_zeroH<<<(NN * NB + 255) / 256, 256>>>(H, Hhi, Hlo);
    for (int t = 0; t < TT; t++) {
        k_mma<<<dim3(NB / 128, 7), 256>>>(Ahi, Alo, Hhi, Hlo, AHhi, AHlo, NB);
        k_pn<128, false, true><<<NN, 128>>>(X0hi, X0lo, NC0, (size_t)t * 64,
            Hhi, Hlo, AX0hi, AX0lo, NC0, (size_t)t * 64, AHhi, AHlo,
            WG0h, WG0l, Bg0, R, H, ZHhi, ZHlo, (bf16*)0, (bf16*)0, 0);
        k_mma<<<dim3(NB / 128, 7), 256>>>(Ahi, Alo, ZHhi, ZHlo, AZHhi, AZHlo, NB);
        k_pn<64, true, true><<<NN, 128>>>(X0hi, X0lo, NC0, (size_t)t * 64,
            ZHhi, ZHlo, AX0hi, AX0lo, NC0, (size_t)t * 64, AZHhi, AZHlo,
            WC0h, WC0l, Bc0, R, H, Hhi, Hlo, Shi, Slo, (size_t)t * NB);
    }

    k_mma<<<dim3(NCSEQ / 128, 7), 256>>>(Ahi, Alo, Shi, Slo, AShi, ASlo, NCSEQ);

    // layer 1
    k_zeroH<<<(NN * NB + 255) / 256, 256>>>(H, Hhi, Hlo);
    for (int t = 0; t < TT; t++) {
        k_mma<<<dim3(NB / 128, 7), 256>>>(Ahi, Alo, Hhi, Hlo, AHhi, AHlo, NB);
        k_pn<128, false, false><<<NN, 128>>>(Shi, Slo, NCSEQ, (size_t)t * NB,
            Hhi, Hlo, AShi, ASlo, NCSEQ, (size_t)t * NB, AHhi, AHlo,
            WG1h, WG1l, Bg1, R, H, ZHhi, ZHlo, (bf16*)0, (bf16*)0, 0);
        k_mma<<<dim3(NB / 128, 7), 256>>>(Ahi, Alo, ZHhi, ZHlo, AZHhi, AZHlo, NB);
        k_pn<64, true, false><<<NN, 128>>>(Shi, Slo, NCSEQ, (size_t)t * NB,
            ZHhi, ZHlo, AShi, ASlo, NCSEQ, (size_t)t * NB, AZHhi, AZHlo,
            WC1h, WC1l, Bc1, R, H, Hhi, Hlo, (bf16*)0, (bf16*)0, 0);
    }

    k_final<<<(BB * NN + 255) / 256, 256>>>(H, cw, cb, out);
}